// round 10
// baseline (speedup 1.0000x reference)
#include <cuda_runtime.h>
#include <cstdint>

// Burden_29145648070955:  output = s_21 of the scalar map
//   s_{t+1} = (X.w + b) + 0.5*||w||^2 * nab(s_t),  nab(z)=0.5*(z+1)*rsqrt((z+1)^2+1)
// One streaming matvec over X[65536,1024] (256 MB single pass) + per-row
// scalar recurrence. Memory-ceiling bound (~6.4 TB/s measured, 8 variants).
//
// R10: last untested lever — Blackwell 256-bit global loads
// (ld.global.cs.v8.f32): 8 loads/row instead of 16, 1KB/warp/instruction.
// Sector traffic identical; tests whether any of the residual ~19%
// DRAM-idle is per-request LSU/L1tex-queue overhead.

#define BATCH   65536
#define DIM     1024
#define THREADS 128
#define ROWS_PER_WARP  32
#define ROWS_PER_BLOCK 128
#define GRID    (BATCH / ROWS_PER_BLOCK)   // 512
#define NITERS  21                          // 20 CCP steps + final apply

struct F8 { float v[8]; };

__device__ __forceinline__ void ldg256_cs(F8& d, const float* __restrict__ p)
{
    asm volatile("ld.global.cs.v8.f32 {%0,%1,%2,%3,%4,%5,%6,%7}, [%8];"
                 : "=f"(d.v[0]), "=f"(d.v[1]), "=f"(d.v[2]), "=f"(d.v[3]),
                   "=f"(d.v[4]), "=f"(d.v[5]), "=f"(d.v[6]), "=f"(d.v[7])
                 : "l"(p));
}

__device__ __forceinline__ void ldg256(F8& d, const float* __restrict__ p)
{
    asm volatile("ld.global.v8.f32 {%0,%1,%2,%3,%4,%5,%6,%7}, [%8];"
                 : "=f"(d.v[0]), "=f"(d.v[1]), "=f"(d.v[2]), "=f"(d.v[3]),
                   "=f"(d.v[4]), "=f"(d.v[5]), "=f"(d.v[6]), "=f"(d.v[7])
                 : "l"(p));
}

// dot of one row fragment (4 x 8 floats) against w fragment: 4 partials
__device__ __forceinline__ float dot4o(const F8* __restrict__ x,
                                       const F8* __restrict__ w)
{
    float p0 = 0.f, p1 = 0.f, p2 = 0.f, p3 = 0.f;
#pragma unroll
    for (int k = 0; k < 4; k++) {
        p0 += x[k].v[0] * w[k].v[0] + x[k].v[4] * w[k].v[4];
        p1 += x[k].v[1] * w[k].v[1] + x[k].v[5] * w[k].v[5];
        p2 += x[k].v[2] * w[k].v[2] + x[k].v[6] * w[k].v[6];
        p3 += x[k].v[3] * w[k].v[3] + x[k].v[7] * w[k].v[7];
    }
    return (p0 + p1) + (p2 + p3);
}

__global__ void __launch_bounds__(THREADS, 4)
burden_kernel(const float* __restrict__ X,
              const float* __restrict__ w,
              const float* __restrict__ b,
              float* __restrict__ out)
{
    const int lane    = threadIdx.x & 31;
    const int warp    = threadIdx.x >> 5;
    const int rowBase = blockIdx.x * ROWS_PER_BLOCK + warp * ROWS_PER_WARP;

    // ---- w fragment in registers: lane owns 8-float octets lane+32k ----
    F8 w4[4];
#pragma unroll
    for (int k = 0; k < 4; k++) ldg256(w4[k], w + (lane + 32 * k) * 8);

    // ---- ww = ||w||^2 (butterfly, all lanes) ----
    float wwp = dot4o(w4, w4);
#pragma unroll
    for (int o = 16; o > 0; o >>= 1) wwp += __shfl_xor_sync(0xffffffffu, wwp, o);
    const float ww = wwp;
    const float b0 = b[0];

    const float* base = X + (size_t)rowBase * DIM;

    // ---- pipelined row dots: A/B double buffer (4 LDG.256 each) ----
    F8 A[4], B[4];
#pragma unroll
    for (int k = 0; k < 4; k++) ldg256_cs(A[k], base + (lane + 32 * k) * 8);

    float myS = 0.f;   // lane j ends holding s0 for row rowBase + j
#pragma unroll 1
    for (int j = 0; j < ROWS_PER_WARP; j += 2) {
        // prefetch row j+1 into B
        const float* pB = base + (size_t)(j + 1) * DIM;
#pragma unroll
        for (int k = 0; k < 4; k++) ldg256_cs(B[k], pB + (lane + 32 * k) * 8);

        float a0 = dot4o(A, w4);              // row j (A resident)

        // prefetch row j+2 into A (off on last iteration)
        if (j + 2 < ROWS_PER_WARP) {
            const float* pA = base + (size_t)(j + 2) * DIM;
#pragma unroll
            for (int k = 0; k < 4; k++) ldg256_cs(A[k], pA + (lane + 32 * k) * 8);
        }

        float a1 = dot4o(B, w4);              // row j+1

        // merged 2-row reduction: 6 shuffles
        a0 += __shfl_xor_sync(0xffffffffu, a0, 1);
        a1 += __shfl_xor_sync(0xffffffffu, a1, 1);
        float v = (lane & 1) ? a1 : a0;
#pragma unroll
        for (int o = 2; o <= 16; o <<= 1)
            v += __shfl_xor_sync(0xffffffffu, v, o);
        // even lanes hold sum(row j), odd lanes sum(row j+1)
        if ((lane & ~1) == j) myS = v;
    }

    // ---- lane-parallel scalar CCP recurrence ----
    const float t0 = myS + b0;
    const float c  = 0.5f * ww;
    float s = t0;
#pragma unroll
    for (int it = 0; it < NITERS; it++) {
        float z   = s + 1.0f;                        // slope = 1
        float nab = 0.5f * z * rsqrtf(z * z + 1.0f);
        s = t0 + c * nab;
    }
    out[rowBase + lane] = s;   // coalesced 128B per warp
}

extern "C" void kernel_launch(void* const* d_in, const int* in_sizes, int n_in,
                              void* d_out, int out_size)
{
    const float* X = (const float*)d_in[0];
    const float* w = (const float*)d_in[1];
    const float* b = (const float*)d_in[2];
    float* out = (float*)d_out;
    (void)in_sizes; (void)n_in; (void)out_size;

    burden_kernel<<<GRID, THREADS>>>(X, w, b, out);
}

// round 11
// speedup vs baseline: 1.0124x; 1.0124x over previous
#include <cuda_runtime.h>
#include <cstdint>

// Burden_29145648070955 — FINAL (converged at the chip's memory-path ceiling)
//
// Math reduction: the CCP fixed point x_{t+1} = X + 0.5*nab(x_t.w+b)*w moves x
// only along w, so s_t = x_t.w + b obeys the scalar map
//   s_{t+1} = (X.w + b) + 0.5*||w||^2 * nab(s_t),  nab(z)=0.5*(z+1)*rsqrt((z+1)^2+1)
// and the final score X_opt.w + b is exactly s_21. Kernel = one streaming
// matvec over X[65536,1024] (256 MB, single pass, zero reuse) + a
// lane-parallel 21-step scalar recurrence. This removes the reference's 21
// full passes over X (~20x traffic reduction vs a direct port).
//
// Convergence evidence (10 rounds): every structural variant — batch-MLP vs
// A/B double buffer, occupancy 16-20 warps/SM, grids 512/592/1024 incl.
// persistent balanced split, prologue/tail scheduling, scalar vs packed
// FFMA2, LDG.128 vs LDG.256 — lands in 43.5-44.4 us bench at 6.1-6.44 TB/s.
// Sector-bound at the path-independent LTS/HBM achieved ceiling;
// 268 MB / ~6.2 TB/s ~= 43 us floor. This variant measured best:
// bench 43.52 us, ncu 42.2 us, DRAM 81.2%, issue 6.4%.
//
// Structure: grid 512 x 128 thr (32 rows/warp); w fragment in registers;
// A/B register double buffer keeps ~8 LDG.128 in flight through the
// dependent dot window; packed f32x2 FMA (sm_10x FFMA2 via PTX) halves the
// FMA stream; merged 2-row reduction in 6 shuffles; __ldcs streams X past
// L2 (zero reuse); coalesced 128B store per warp.

#define BATCH   65536
#define DIM     1024
#define DIMV    (DIM / 4)       // 256 x 16B per row
#define THREADS 128
#define ROWS_PER_WARP  32
#define ROWS_PER_BLOCK 128
#define GRID    (BATCH / ROWS_PER_BLOCK)   // 512
#define NITERS  21                          // 20 CCP steps + final apply

__device__ __forceinline__ uint64_t fma2(uint64_t a, uint64_t b, uint64_t c)
{
    uint64_t d;
    asm("fma.rn.f32x2 %0, %1, %2, %3;" : "=l"(d) : "l"(a), "l"(b), "l"(c));
    return d;
}

__device__ __forceinline__ float unpack_sum(uint64_t a, uint64_t b)
{
    float a0, a1, b0, b1;
    asm("mov.b64 {%0, %1}, %2;" : "=f"(a0), "=f"(a1) : "l"(a));
    asm("mov.b64 {%0, %1}, %2;" : "=f"(b0), "=f"(b1) : "l"(b));
    return (a0 + a1) + (b0 + b1);
}

// dot of one row fragment (8 x 16B) against w fragment: 16 FFMA2
__device__ __forceinline__ float dot8p(const ulonglong2* __restrict__ x,
                                       const ulonglong2* __restrict__ w)
{
    uint64_t acc0 = 0ull, acc1 = 0ull;   // packed (0.f, 0.f)
#pragma unroll
    for (int k = 0; k < 8; k++) {
        acc0 = fma2(x[k].x, w[k].x, acc0);
        acc1 = fma2(x[k].y, w[k].y, acc1);
    }
    return unpack_sum(acc0, acc1);
}

__global__ void __launch_bounds__(THREADS, 4)
burden_kernel(const float* __restrict__ X,
              const float* __restrict__ w,
              const float* __restrict__ b,
              float* __restrict__ out)
{
    const int lane    = threadIdx.x & 31;
    const int warp    = threadIdx.x >> 5;
    const int rowBase = blockIdx.x * ROWS_PER_BLOCK + warp * ROWS_PER_WARP;

    // ---- w fragment in registers: lane owns 16B columns lane+32k ----
    const ulonglong2* wvp = reinterpret_cast<const ulonglong2*>(w);
    ulonglong2 w4[8];
#pragma unroll
    for (int k = 0; k < 8; k++) w4[k] = wvp[lane + 32 * k];

    // ---- ww = ||w||^2 (butterfly, all lanes) ----
    float wwp = dot8p(w4, w4);
#pragma unroll
    for (int o = 16; o > 0; o >>= 1) wwp += __shfl_xor_sync(0xffffffffu, wwp, o);
    const float ww = wwp;
    const float b0 = b[0];

    const ulonglong2* base = reinterpret_cast<const ulonglong2*>(X)
                           + (size_t)rowBase * DIMV;

    // ---- pipelined row dots: A/B double buffer ----
    ulonglong2 A[8], B[8];
#pragma unroll
    for (int k = 0; k < 8; k++) A[k] = __ldcs(base + lane + 32 * k);  // row 0

    float myS = 0.f;   // lane j ends holding s0 for row rowBase + j
#pragma unroll 1
    for (int j = 0; j < ROWS_PER_WARP; j += 2) {
        // prefetch row j+1 into B
        const ulonglong2* pB = base + (size_t)(j + 1) * DIMV;
#pragma unroll
        for (int k = 0; k < 8; k++) B[k] = __ldcs(pB + lane + 32 * k);

        float a0 = dot8p(A, w4);              // row j (A resident)

        // prefetch row j+2 into A (off on last iteration)
        if (j + 2 < ROWS_PER_WARP) {
            const ulonglong2* pA = base + (size_t)(j + 2) * DIMV;
#pragma unroll
            for (int k = 0; k < 8; k++) A[k] = __ldcs(pA + lane + 32 * k);
        }

        float a1 = dot8p(B, w4);              // row j+1

        // merged 2-row reduction: 6 shuffles
        a0 += __shfl_xor_sync(0xffffffffu, a0, 1);
        a1 += __shfl_xor_sync(0xffffffffu, a1, 1);
        float v = (lane & 1) ? a1 : a0;
#pragma unroll
        for (int o = 2; o <= 16; o <<= 1)
            v += __shfl_xor_sync(0xffffffffu, v, o);
        // even lanes hold sum(row j), odd lanes sum(row j+1)
        if ((lane & ~1) == j) myS = v;
    }

    // ---- lane-parallel scalar CCP recurrence ----
    const float t0 = myS + b0;
    const float c  = 0.5f * ww;
    float s = t0;
#pragma unroll
    for (int it = 0; it < NITERS; it++) {
        float z   = s + 1.0f;                        // slope = 1
        float nab = 0.5f * z * rsqrtf(z * z + 1.0f);
        s = t0 + c * nab;
    }
    out[rowBase + lane] = s;   // coalesced 128B per warp
}

extern "C" void kernel_launch(void* const* d_in, const int* in_sizes, int n_in,
                              void* d_out, int out_size)
{
    const float* X = (const float*)d_in[0];
    const float* w = (const float*)d_in[1];
    const float* b = (const float*)d_in[2];
    float* out = (float*)d_out;
    (void)in_sizes; (void)n_in; (void)out_size;

    burden_kernel<<<GRID, THREADS>>>(X, w, b, out);
}

// round 12
// speedup vs baseline: 1.0199x; 1.0074x over previous
#include <cuda_runtime.h>
#include <cstdint>

// Burden_29145648070955 — FINAL (converged at the chip's memory-path ceiling)
//
// Math reduction: the CCP fixed point x_{t+1} = X + 0.5*nab(x_t.w+b)*w moves x
// only along w, so s_t = x_t.w + b obeys the scalar map
//   s_{t+1} = (X.w + b) + 0.5*||w||^2 * nab(s_t),  nab(z)=0.5*(z+1)*rsqrt((z+1)^2+1)
// and the final score X_opt.w + b is exactly s_21. Kernel = one streaming
// matvec over X[65536,1024] (256 MB, single pass, zero reuse) + a
// lane-parallel 21-step scalar recurrence (~20x traffic cut vs direct port).
//
// Convergence (11 rounds): batch-MLP vs A/B double buffer, occupancy 16-20
// warps/SM, grids 512/592/1024 incl. persistent balanced split, prologue/
// tail scheduling, scalar vs packed FFMA2, LDG.128 vs LDG.256 — all within
// 43.5-44.4 us bench at 6.1-6.44 TB/s. Sector-bound at the path-independent
// LTS/HBM achieved ceiling; 268 MB / ~6.2 TB/s ~= 43 us floor. This variant
// measured best: bench 43.52 us (x2), ncu 42.2 us, DRAM 81.2%, issue 6.4%.
//
// Structure: grid 512 x 128 thr (32 rows/warp); w fragment in registers;
// A/B register double buffer keeps ~8 LDG.128 in flight through the
// dependent dot window; packed f32x2 FMA (sm_10x FFMA2 via PTX) halves the
// FMA stream; merged 2-row reduction in 6 shuffles; __ldcs streams X past
// L2 (zero reuse); coalesced 128B store per warp.

#define BATCH   65536
#define DIM     1024
#define DIMV    (DIM / 4)       // 256 x 16B per row
#define THREADS 128
#define ROWS_PER_WARP  32
#define ROWS_PER_BLOCK 128
#define GRID    (BATCH / ROWS_PER_BLOCK)   // 512
#define NITERS  21                          // 20 CCP steps + final apply

__device__ __forceinline__ uint64_t fma2(uint64_t a, uint64_t b, uint64_t c)
{
    uint64_t d;
    asm("fma.rn.f32x2 %0, %1, %2, %3;" : "=l"(d) : "l"(a), "l"(b), "l"(c));
    return d;
}

__device__ __forceinline__ float unpack_sum(uint64_t a, uint64_t b)
{
    float a0, a1, b0, b1;
    asm("mov.b64 {%0, %1}, %2;" : "=f"(a0), "=f"(a1) : "l"(a));
    asm("mov.b64 {%0, %1}, %2;" : "=f"(b0), "=f"(b1) : "l"(b));
    return (a0 + a1) + (b0 + b1);
}

// dot of one row fragment (8 x 16B) against w fragment: 16 FFMA2
__device__ __forceinline__ float dot8p(const ulonglong2* __restrict__ x,
                                       const ulonglong2* __restrict__ w)
{
    uint64_t acc0 = 0ull, acc1 = 0ull;   // packed (0.f, 0.f)
#pragma unroll
    for (int k = 0; k < 8; k++) {
        acc0 = fma2(x[k].x, w[k].x, acc0);
        acc1 = fma2(x[k].y, w[k].y, acc1);
    }
    return unpack_sum(acc0, acc1);
}

__global__ void __launch_bounds__(THREADS, 4)
burden_kernel(const float* __restrict__ X,
              const float* __restrict__ w,
              const float* __restrict__ b,
              float* __restrict__ out)
{
    const int lane    = threadIdx.x & 31;
    const int warp    = threadIdx.x >> 5;
    const int rowBase = blockIdx.x * ROWS_PER_BLOCK + warp * ROWS_PER_WARP;

    // ---- w fragment in registers: lane owns 16B columns lane+32k ----
    const ulonglong2* wvp = reinterpret_cast<const ulonglong2*>(w);
    ulonglong2 w4[8];
#pragma unroll
    for (int k = 0; k < 8; k++) w4[k] = wvp[lane + 32 * k];

    // ---- ww = ||w||^2 (butterfly, all lanes) ----
    float wwp = dot8p(w4, w4);
#pragma unroll
    for (int o = 16; o > 0; o >>= 1) wwp += __shfl_xor_sync(0xffffffffu, wwp, o);
    const float ww = wwp;
    const float b0 = b[0];

    const ulonglong2* base = reinterpret_cast<const ulonglong2*>(X)
                           + (size_t)rowBase * DIMV;

    // ---- pipelined row dots: A/B double buffer ----
    ulonglong2 A[8], B[8];
#pragma unroll
    for (int k = 0; k < 8; k++) A[k] = __ldcs(base + lane + 32 * k);  // row 0

    float myS = 0.f;   // lane j ends holding s0 for row rowBase + j
#pragma unroll 1
    for (int j = 0; j < ROWS_PER_WARP; j += 2) {
        // prefetch row j+1 into B
        const ulonglong2* pB = base + (size_t)(j + 1) * DIMV;
#pragma unroll
        for (int k = 0; k < 8; k++) B[k] = __ldcs(pB + lane + 32 * k);

        float a0 = dot8p(A, w4);              // row j (A resident)

        // prefetch row j+2 into A (off on last iteration)
        if (j + 2 < ROWS_PER_WARP) {
            const ulonglong2* pA = base + (size_t)(j + 2) * DIMV;
#pragma unroll
            for (int k = 0; k < 8; k++) A[k] = __ldcs(pA + lane + 32 * k);
        }

        float a1 = dot8p(B, w4);              // row j+1

        // merged 2-row reduction: 6 shuffles
        a0 += __shfl_xor_sync(0xffffffffu, a0, 1);
        a1 += __shfl_xor_sync(0xffffffffu, a1, 1);
        float v = (lane & 1) ? a1 : a0;
#pragma unroll
        for (int o = 2; o <= 16; o <<= 1)
            v += __shfl_xor_sync(0xffffffffu, v, o);
        // even lanes hold sum(row j), odd lanes sum(row j+1)
        if ((lane & ~1) == j) myS = v;
    }

    // ---- lane-parallel scalar CCP recurrence ----
    const float t0 = myS + b0;
    const float c  = 0.5f * ww;
    float s = t0;
#pragma unroll
    for (int it = 0; it < NITERS; it++) {
        float z   = s + 1.0f;                        // slope = 1
        float nab = 0.5f * z * rsqrtf(z * z + 1.0f);
        s = t0 + c * nab;
    }
    out[rowBase + lane] = s;   // coalesced 128B per warp
}

extern "C" void kernel_launch(void* const* d_in, const int* in_sizes, int n_in,
                              void* d_out, int out_size)
{
    const float* X = (const float*)d_in[0];
    const float* w = (const float*)d_in[1];
    const float* b = (const float*)d_in[2];
    float* out = (float*)d_out;
    (void)in_sizes; (void)n_in; (void)out_size;

    burden_kernel<<<GRID, THREADS>>>(X, w, b, out);
}